// round 4
// baseline (speedup 1.0000x reference)
#include <cuda_runtime.h>

#define NB     256
#define NPIX   (1024*1024)
#define NBATCH 16
#define G      2                 // images per group (25 MB input — L2 reuse safe)
#define NGROUP (NBATCH / G)
#define IT     2                 // 8-float items per thread (16 px/thread/channel)
#define TPB    256
#define BLKX   (NPIX / 8 / (TPB * IT))   // 256 blocks per image

// Scratch (no allocations allowed). g_histo is zero at module load and re-zeroed
// by lut_kernel after consumption, so every graph replay sees zeros.
__device__ int   g_histo[NBATCH][NB];
__device__ float g_lut[NBATCH][NB];
__device__ float g_step[NBATCH];

__device__ __forceinline__ float clip01(float x) {
    return fminf(fmaxf(x, 0.0f), 1.0f);
}

struct f8 { float v[8]; };

// 32-byte load pinning the line in L2 (evict_last). ptxas on sm_103 only
// accepts .v8.b32/.v4.b64 widths with this modifier.
__device__ __forceinline__ f8 ldg_el8(const float* p) {
    unsigned long long a, b, c, d;
    asm volatile("ld.global.L2::evict_last.v4.b64 {%0,%1,%2,%3}, [%4];"
                 : "=l"(a), "=l"(b), "=l"(c), "=l"(d) : "l"(p));
    f8 r;
    r.v[0] = __uint_as_float((unsigned)(a));
    r.v[1] = __uint_as_float((unsigned)(a >> 32));
    r.v[2] = __uint_as_float((unsigned)(b));
    r.v[3] = __uint_as_float((unsigned)(b >> 32));
    r.v[4] = __uint_as_float((unsigned)(c));
    r.v[5] = __uint_as_float((unsigned)(c >> 32));
    r.v[6] = __uint_as_float((unsigned)(d));
    r.v[7] = __uint_as_float((unsigned)(d >> 32));
    return r;
}

// Pass 1: per-image histogram of Y bins. evict_last loads stage the group's
// input in L2 for map_kernel. Warp-aggregated shared atomics.
__global__ void hist_kernel(const float* __restrict__ img, int img_base) {
    __shared__ int sh[NB];
    for (int i = threadIdx.x; i < NB; i += blockDim.x) sh[i] = 0;
    __syncthreads();

    const int b = img_base + blockIdx.y;
    const size_t base = (size_t)b * 3 * NPIX;
    const float* __restrict__ R  = img + base;
    const float* __restrict__ Gc = img + base + NPIX;
    const float* __restrict__ B  = img + base + 2 * NPIX;

    const int tile = blockIdx.x * (TPB * IT);
    const float scale = (float)(256.0 / 255.0);   // NUM_BINS / 255.0 in f32

    #pragma unroll
    for (int k = 0; k < IT; k++) {
        int i = (tile + k * TPB + threadIdx.x) * 8;
        f8 r8 = ldg_el8(R + i), g8 = ldg_el8(Gc + i), b8 = ldg_el8(B + i);
        #pragma unroll
        for (int c = 0; c < 8; c++) {
            float r  = clip01(r8.v[c]);
            float g  = clip01(g8.v[c]);
            float bb = clip01(b8.v[c]);
            float y = 0.299f * r + 0.587f * g + 0.114f * bb;
            int bin = (int)floorf(y * 255.0f * scale);
            bin = min(max(bin, 0), NB - 1);
            // Warp-aggregate: one conflict-free atomic per distinct bin.
            unsigned mask = __match_any_sync(0xffffffffu, bin);
            int leader = __ffs(mask) - 1;
            if ((threadIdx.x & 31) == leader) atomicAdd(&sh[bin], __popc(mask));
        }
    }
    __syncthreads();
    for (int i = threadIdx.x; i < NB; i += blockDim.x)
        if (sh[i]) atomicAdd(&g_histo[b][i], sh[i]);
}

// LUT: one block per image in the group; also resets the histogram for the
// next graph replay.
__global__ void lut_kernel(int img_base) {
    const int b = img_base + blockIdx.x;
    const int t = threadIdx.x;

    __shared__ float h[NB];
    __shared__ float s[NB];
    __shared__ int   lastIdx;

    float hv = (float)g_histo[b][t];
    g_histo[b][t] = 0;                    // reset for next replay
    h[t] = hv;
    s[t] = hv;
    if (t == 0) lastIdx = 0;
    __syncthreads();

    // Inclusive Hillis-Steele scan (fp32 exact: counts < 2^24).
    for (int off = 1; off < NB; off <<= 1) {
        float add = (t >= off) ? s[t - off] : 0.0f;
        __syncthreads();
        s[t] += add;
        __syncthreads();
    }

    if (hv > 0.0f) atomicMax(&lastIdx, t);
    __syncthreads();

    float total    = s[NB - 1];
    float last_val = h[lastIdx];
    float step     = floorf(__fdiv_rn(total - last_val, 255.0f));
    float safe     = fmaxf(step, 1.0f);
    float half     = floorf(__fdiv_rn(step, 2.0f));

    float lv;
    if (t == 0) {
        lv = 0.0f;
    } else {
        lv = floorf(__fdiv_rn(s[t - 1] + half, safe));
        lv = fminf(fmaxf(lv, 0.0f), 255.0f);
    }
    g_lut[b][t] = lv;
    if (t == 0) g_step[b] = step;
}

// Pass 2: map Y through LUT, recombine with U/V, convert back to RGB.
// __ldcs: input is last-touch (staged by hist, demote after read).
// __stcs: output is never re-read — streaming store preserves L2 for staging.
__global__ void map_kernel(const float* __restrict__ img, float* __restrict__ out,
                           int img_base) {
    __shared__ float lut[NB];
    __shared__ float stepv;

    const int b = img_base + blockIdx.y;
    for (int i = threadIdx.x; i < NB; i += blockDim.x) lut[i] = g_lut[b][i];
    if (threadIdx.x == 0) stepv = g_step[b];
    __syncthreads();

    const bool identity = (stepv == 0.0f);

    const size_t base = (size_t)b * 3 * NPIX;
    const float4* __restrict__ R  = (const float4*)(img + base);
    const float4* __restrict__ Gc = (const float4*)(img + base + NPIX);
    const float4* __restrict__ B  = (const float4*)(img + base + 2 * NPIX);
    float4* __restrict__ Ro = (float4*)(out + base);
    float4* __restrict__ Go = (float4*)(out + base + NPIX);
    float4* __restrict__ Bo = (float4*)(out + base + 2 * NPIX);

    const int tile = blockIdx.x * (TPB * IT * 2);   // 2 float4 per f8 slot
    const float inv255 = 1.0f / 255.0f;   // 1-ulp from /255 — within 1e-3 tol

    #pragma unroll
    for (int k = 0; k < IT * 2; k++) {
        int i = tile + k * TPB + threadIdx.x;
        float4 r4 = __ldcs(R + i);
        float4 g4 = __ldcs(Gc + i);
        float4 b4 = __ldcs(B + i);
        float4 ro, go, bo;
        #pragma unroll
        for (int c = 0; c < 4; c++) {
            float r  = clip01(((const float*)&r4)[c]);
            float g  = clip01(((const float*)&g4)[c]);
            float bb = clip01(((const float*)&b4)[c]);

            float y = 0.299f * r + 0.587f * g + 0.114f * bb;
            float u = -0.147f * r - 0.289f * g + 0.436f * bb;
            float v = 0.615f * r - 0.515f * g - 0.100f * bb;

            float t = y * 255.0f;
            int gi = min(max((int)t, 0), NB - 1);
            float outv = identity ? t : lut[gi];
            float ye = outv * inv255;

            ((float*)&ro)[c] = ye + 1.14f * v;
            ((float*)&go)[c] = ye - 0.396f * u - 0.581f * v;
            ((float*)&bo)[c] = ye + 2.029f * u;
        }
        __stcs(Ro + i, ro);
        __stcs(Go + i, go);
        __stcs(Bo + i, bo);
    }
}

// Lazy one-time resources (created on the correctness call, outside capture).
static bool         g_inited = false;
static cudaStream_t g_s1;
static cudaEvent_t  g_evLut[NGROUP];
static cudaEvent_t  g_evDone;

extern "C" void kernel_launch(void* const* d_in, const int* in_sizes, int n_in,
                              void* d_out, int out_size) {
    const float* img = (const float*)d_in[0];
    float*       out = (float*)d_out;

    if (!g_inited) {
        cudaStreamCreateWithFlags(&g_s1, cudaStreamNonBlocking);
        for (int g = 0; g < NGROUP; g++)
            cudaEventCreateWithFlags(&g_evLut[g], cudaEventDisableTiming);
        cudaEventCreateWithFlags(&g_evDone, cudaEventDisableTiming);
        g_inited = true;
    }

    // Pipeline: hist(g)+lut(g) on the origin stream; map(g) on g_s1 gated by
    // lut(g). hist(g+1) overlaps map(g). Joined at the end so capture sees a
    // single connected graph.
    for (int g = 0; g < NGROUP; g++) {
        dim3 grid(BLKX, G);
        hist_kernel<<<grid, TPB>>>(img, g * G);
        lut_kernel<<<G, NB>>>(g * G);
        cudaEventRecord(g_evLut[g], 0);
        cudaStreamWaitEvent(g_s1, g_evLut[g], 0);
        map_kernel<<<grid, TPB, 0, g_s1>>>(img, out, g * G);
    }
    cudaEventRecord(g_evDone, g_s1);
    cudaStreamWaitEvent(0, g_evDone, 0);
}

// round 5
// speedup vs baseline: 1.5521x; 1.5521x over previous
#include <cuda_runtime.h>

#define NB     256
#define NPIX   (1024*1024)
#define NBATCH 16
#define G      2                  // images per group (25 MB input — L2 reuse)
#define NGROUP (NBATCH / G)
#define IT     2                  // float4 items per thread
#define TPB    256
#define BLKX   (NPIX / 4 / (TPB * IT))   // 512 blocks per image

// Scratch (no allocations). All of these are restored to zero within each
// replay (last hist block consumes + resets), so graph replays are identical.
__device__ int   g_histo[NBATCH][NB];
__device__ int   g_count[NBATCH];
__device__ float g_lut[NBATCH][NB];
__device__ float g_step[NBATCH];

__device__ __forceinline__ float clip01(float x) {
    return fminf(fmaxf(x, 0.0f), 1.0f);
}

// Pass 1: per-image histogram of Y bins; the LAST block of each image also
// computes the LUT in-place (ticket pattern) — no separate lut launch.
__global__ void hist_kernel(const float* __restrict__ img, int img_base) {
    __shared__ int   sub[4 * NB];     // 4 sub-histograms to cut atomic conflicts
    __shared__ float h[NB];
    __shared__ float s[NB];
    __shared__ int   lastIdx;
    __shared__ int   isLast;

    for (int i = threadIdx.x; i < 4 * NB; i += TPB) sub[i] = 0;
    __syncthreads();

    const int b = img_base + blockIdx.y;
    const size_t base = (size_t)b * 3 * NPIX;
    const float4* __restrict__ R  = (const float4*)(img + base);
    const float4* __restrict__ Gc = (const float4*)(img + base + NPIX);
    const float4* __restrict__ B  = (const float4*)(img + base + 2 * NPIX);

    const int tile = blockIdx.x * (TPB * IT);
    const float scale = (float)(256.0 / 255.0);   // NUM_BINS / 255.0 in f32
    int* mysub = &sub[((threadIdx.x >> 5) & 3) * NB];

    #pragma unroll
    for (int k = 0; k < IT; k++) {
        int i = tile + k * TPB + threadIdx.x;
        float4 r4 = R[i], g4 = Gc[i], b4 = B[i];
        #pragma unroll
        for (int c = 0; c < 4; c++) {
            float r  = clip01(((const float*)&r4)[c]);
            float g  = clip01(((const float*)&g4)[c]);
            float bb = clip01(((const float*)&b4)[c]);
            float y = 0.299f * r + 0.587f * g + 0.114f * bb;
            int bin = (int)floorf(y * 255.0f * scale);
            bin = min(max(bin, 0), NB - 1);
            atomicAdd(&mysub[bin], 1);
        }
    }
    __syncthreads();

    {   // merge sub-histograms and publish (TPB == NB)
        int t = threadIdx.x;
        int tot = sub[t] + sub[NB + t] + sub[2 * NB + t] + sub[3 * NB + t];
        if (tot) atomicAdd(&g_histo[b][t], tot);
    }
    __threadfence();

    if (threadIdx.x == 0) {
        isLast = (atomicAdd(&g_count[b], 1) == (BLKX - 1));
        lastIdx = 0;
    }
    __syncthreads();
    if (!isLast) return;

    // ---- Last block: compute LUT for image b ----
    const int t = threadIdx.x;
    float hv = (float)__ldcg(&g_histo[b][t]);   // bypass L1 (other SMs wrote)
    g_histo[b][t] = 0;                          // reset for next replay
    h[t] = hv;
    s[t] = hv;
    __syncthreads();

    // Inclusive Hillis-Steele scan (fp32 exact: counts < 2^24).
    for (int off = 1; off < NB; off <<= 1) {
        float add = (t >= off) ? s[t - off] : 0.0f;
        __syncthreads();
        s[t] += add;
        __syncthreads();
    }

    if (hv > 0.0f) atomicMax(&lastIdx, t);
    __syncthreads();

    float total    = s[NB - 1];
    float last_val = h[lastIdx];
    float step     = floorf(__fdiv_rn(total - last_val, 255.0f));
    float safe     = fmaxf(step, 1.0f);
    float half     = floorf(__fdiv_rn(step, 2.0f));

    float lv;
    if (t == 0) {
        lv = 0.0f;
    } else {
        lv = floorf(__fdiv_rn(s[t - 1] + half, safe));
        lv = fminf(fmaxf(lv, 0.0f), 255.0f);
    }
    g_lut[b][t] = lv;
    if (t == 0) {
        g_step[b]  = step;
        g_count[b] = 0;                         // reset ticket for next replay
    }
}

// Pass 2: map Y through LUT, recombine with U/V, convert back to RGB.
// __ldcs: input is last-touch (staged in L2 by hist, demote after read).
// __stcs: output is never re-read — evict-first preserves L2 for staging.
__global__ void map_kernel(const float* __restrict__ img, float* __restrict__ out,
                           int img_base) {
    __shared__ float lut[NB];
    __shared__ float stepv;

    const int b = img_base + blockIdx.y;
    for (int i = threadIdx.x; i < NB; i += TPB) lut[i] = g_lut[b][i];
    if (threadIdx.x == 0) stepv = g_step[b];
    __syncthreads();

    const bool identity = (stepv == 0.0f);

    const size_t base = (size_t)b * 3 * NPIX;
    const float4* __restrict__ R  = (const float4*)(img + base);
    const float4* __restrict__ Gc = (const float4*)(img + base + NPIX);
    const float4* __restrict__ B  = (const float4*)(img + base + 2 * NPIX);
    float4* __restrict__ Ro = (float4*)(out + base);
    float4* __restrict__ Go = (float4*)(out + base + NPIX);
    float4* __restrict__ Bo = (float4*)(out + base + 2 * NPIX);

    const int tile = blockIdx.x * (TPB * IT);
    const float inv255 = 1.0f / 255.0f;

    #pragma unroll
    for (int k = 0; k < IT; k++) {
        int i = tile + k * TPB + threadIdx.x;
        float4 r4 = __ldcs(R + i);
        float4 g4 = __ldcs(Gc + i);
        float4 b4 = __ldcs(B + i);
        float4 ro, go, bo;
        #pragma unroll
        for (int c = 0; c < 4; c++) {
            float r  = clip01(((const float*)&r4)[c]);
            float g  = clip01(((const float*)&g4)[c]);
            float bb = clip01(((const float*)&b4)[c]);

            float y = 0.299f * r + 0.587f * g + 0.114f * bb;
            float u = -0.147f * r - 0.289f * g + 0.436f * bb;
            float v = 0.615f * r - 0.515f * g - 0.100f * bb;

            float t = y * 255.0f;
            int gi = min(max((int)t, 0), NB - 1);
            float outv = identity ? t : lut[gi];
            float ye = outv * inv255;

            ((float*)&ro)[c] = ye + 1.14f * v;
            ((float*)&go)[c] = ye - 0.396f * u - 0.581f * v;
            ((float*)&bo)[c] = ye + 2.029f * u;
        }
        __stcs(Ro + i, ro);
        __stcs(Go + i, go);
        __stcs(Bo + i, bo);
    }
}

// Lazy one-time resources (created on the correctness call, outside capture).
static bool         g_inited = false;
static cudaStream_t g_s1;
static cudaEvent_t  g_evHist[NGROUP];
static cudaEvent_t  g_evDone;

extern "C" void kernel_launch(void* const* d_in, const int* in_sizes, int n_in,
                              void* d_out, int out_size) {
    const float* img = (const float*)d_in[0];
    float*       out = (float*)d_out;

    if (!g_inited) {
        cudaStreamCreateWithFlags(&g_s1, cudaStreamNonBlocking);
        for (int g = 0; g < NGROUP; g++)
            cudaEventCreateWithFlags(&g_evHist[g], cudaEventDisableTiming);
        cudaEventCreateWithFlags(&g_evDone, cudaEventDisableTiming);
        g_inited = true;
    }

    // Pipeline: hist(g) (incl. inline LUT) on the origin stream; map(g) on
    // g_s1 gated by hist(g). hist(g+1) overlaps map(g).
    for (int g = 0; g < NGROUP; g++) {
        dim3 grid(BLKX, G);
        hist_kernel<<<grid, TPB>>>(img, g * G);
        cudaEventRecord(g_evHist[g], 0);
        cudaStreamWaitEvent(g_s1, g_evHist[g], 0);
        map_kernel<<<grid, TPB, 0, g_s1>>>(img, out, g * G);
    }
    cudaEventRecord(g_evDone, g_s1);
    cudaStreamWaitEvent(0, g_evDone, 0);
}

// round 6
// speedup vs baseline: 2.1178x; 1.3645x over previous
#include <cuda_runtime.h>

#define NB     256
#define NPIX   (1024*1024)
#define NBATCH 16
#define G      8                  // images per group: 100 MB input, fits 126 MB L2
#define NGROUP (NBATCH / G)
#define IT     2                  // float4 items per thread
#define TPB    256
#define BLKX   (NPIX / 4 / (TPB * IT))   // 512 blocks per image
#define NSUB   8                  // one sub-histogram per warp

// Scratch (no allocations). g_histo is zero at load and re-zeroed by
// lut_kernel after consumption, so every graph replay sees zeros.
__device__ int   g_histo[NBATCH][NB];
__device__ float g_lut[NBATCH][NB];
__device__ float g_step[NBATCH];

__device__ __forceinline__ float clip01(float x) {
    return fminf(fmaxf(x, 0.0f), 1.0f);
}

// Pass 1: per-image histogram of Y bins. Full-batch-scale grid (4096 blocks)
// so DRAM saturates; per-warp sub-histograms kill inter-warp atomic conflicts.
__global__ void hist_kernel(const float* __restrict__ img, int img_base) {
    __shared__ int sub[NSUB * NB];    // 8 KB
    for (int i = threadIdx.x; i < NSUB * NB; i += TPB) sub[i] = 0;
    __syncthreads();

    const int b = img_base + blockIdx.y;
    const size_t base = (size_t)b * 3 * NPIX;
    const float4* __restrict__ R  = (const float4*)(img + base);
    const float4* __restrict__ Gc = (const float4*)(img + base + NPIX);
    const float4* __restrict__ B  = (const float4*)(img + base + 2 * NPIX);

    const int tile = blockIdx.x * (TPB * IT);
    const float scale = (float)(256.0 / 255.0);   // NUM_BINS / 255.0 in f32
    int* mysub = &sub[(threadIdx.x >> 5) * NB];   // private per warp

    #pragma unroll
    for (int k = 0; k < IT; k++) {
        int i = tile + k * TPB + threadIdx.x;
        float4 r4 = R[i], g4 = Gc[i], b4 = B[i];
        #pragma unroll
        for (int c = 0; c < 4; c++) {
            float r  = clip01(((const float*)&r4)[c]);
            float g  = clip01(((const float*)&g4)[c]);
            float bb = clip01(((const float*)&b4)[c]);
            float y = 0.299f * r + 0.587f * g + 0.114f * bb;
            int bin = (int)floorf(y * 255.0f * scale);
            bin = min(max(bin, 0), NB - 1);
            atomicAdd(&mysub[bin], 1);
        }
    }
    __syncthreads();

    // Merge 8 sub-histograms; one global atomic per bin per block (TPB == NB).
    int t = threadIdx.x;
    int tot = 0;
    #pragma unroll
    for (int w = 0; w < NSUB; w++) tot += sub[w * NB + t];
    if (tot) atomicAdd(&g_histo[b][t], tot);
}

// LUT: one block per image; resets the histogram for the next graph replay.
__global__ void lut_kernel(int img_base) {
    const int b = img_base + blockIdx.x;
    const int t = threadIdx.x;

    __shared__ float h[NB];
    __shared__ float s[NB];
    __shared__ int   lastIdx;

    float hv = (float)g_histo[b][t];
    g_histo[b][t] = 0;                    // reset for next replay
    h[t] = hv;
    s[t] = hv;
    if (t == 0) lastIdx = 0;
    __syncthreads();

    // Inclusive Hillis-Steele scan (fp32 exact: counts < 2^24).
    for (int off = 1; off < NB; off <<= 1) {
        float add = (t >= off) ? s[t - off] : 0.0f;
        __syncthreads();
        s[t] += add;
        __syncthreads();
    }

    if (hv > 0.0f) atomicMax(&lastIdx, t);
    __syncthreads();

    float total    = s[NB - 1];
    float last_val = h[lastIdx];
    float step     = floorf(__fdiv_rn(total - last_val, 255.0f));
    float safe     = fmaxf(step, 1.0f);
    float half     = floorf(__fdiv_rn(step, 2.0f));

    float lv;
    if (t == 0) {
        lv = 0.0f;
    } else {
        lv = floorf(__fdiv_rn(s[t - 1] + half, safe));
        lv = fminf(fmaxf(lv, 0.0f), 255.0f);
    }
    g_lut[b][t] = lv;
    if (t == 0) g_step[b] = step;
}

// Pass 2: map Y through LUT, recombine with U/V, convert back to RGB.
// Reads should hit L2 (staged by hist); __ldcs demotes after the last touch.
// __stcs: output lines evict-first so they never displace staged input.
__global__ void map_kernel(const float* __restrict__ img, float* __restrict__ out,
                           int img_base) {
    __shared__ float lut[NB];
    __shared__ float stepv;

    const int b = img_base + blockIdx.y;
    for (int i = threadIdx.x; i < NB; i += TPB) lut[i] = g_lut[b][i];
    if (threadIdx.x == 0) stepv = g_step[b];
    __syncthreads();

    const bool identity = (stepv == 0.0f);

    const size_t base = (size_t)b * 3 * NPIX;
    const float4* __restrict__ R  = (const float4*)(img + base);
    const float4* __restrict__ Gc = (const float4*)(img + base + NPIX);
    const float4* __restrict__ B  = (const float4*)(img + base + 2 * NPIX);
    float4* __restrict__ Ro = (float4*)(out + base);
    float4* __restrict__ Go = (float4*)(out + base + NPIX);
    float4* __restrict__ Bo = (float4*)(out + base + 2 * NPIX);

    const int tile = blockIdx.x * (TPB * IT);
    const float inv255 = 1.0f / 255.0f;

    #pragma unroll
    for (int k = 0; k < IT; k++) {
        int i = tile + k * TPB + threadIdx.x;
        float4 r4 = __ldcs(R + i);
        float4 g4 = __ldcs(Gc + i);
        float4 b4 = __ldcs(B + i);
        float4 ro, go, bo;
        #pragma unroll
        for (int c = 0; c < 4; c++) {
            float r  = clip01(((const float*)&r4)[c]);
            float g  = clip01(((const float*)&g4)[c]);
            float bb = clip01(((const float*)&b4)[c]);

            float y = 0.299f * r + 0.587f * g + 0.114f * bb;
            float u = -0.147f * r - 0.289f * g + 0.436f * bb;
            float v = 0.615f * r - 0.515f * g - 0.100f * bb;

            float t = y * 255.0f;
            int gi = min(max((int)t, 0), NB - 1);
            float outv = identity ? t : lut[gi];
            float ye = outv * inv255;

            ((float*)&ro)[c] = ye + 1.14f * v;
            ((float*)&go)[c] = ye - 0.396f * u - 0.581f * v;
            ((float*)&bo)[c] = ye + 2.029f * u;
        }
        __stcs(Ro + i, ro);
        __stcs(Go + i, go);
        __stcs(Bo + i, bo);
    }
}

extern "C" void kernel_launch(void* const* d_in, const int* in_sizes, int n_in,
                              void* d_out, int out_size) {
    const float* img = (const float*)d_in[0];
    float*       out = (float*)d_out;

    // Two 100 MB groups, strictly sequential on one stream: hist stages the
    // group in L2, map consumes it from L2. No overlap — keeps the L2
    // footprint to one group + evict-first output.
    for (int g = 0; g < NGROUP; g++) {
        dim3 grid(BLKX, G);
        hist_kernel<<<grid, TPB>>>(img, g * G);
        lut_kernel<<<G, NB>>>(g * G);
        map_kernel<<<grid, TPB>>>(img, out, g * G);
    }
}